// round 15
// baseline (speedup 1.0000x reference)
#include <cuda_runtime.h>

#define NN 50000
#define EE 800000
#define INP 256
#define HH 64
#define BB 4096
#define DD2 192
#define FF 704
#define EPSC 0.3f
#define NEGS 0.3f
#define SCAN_N (3 * NN)
#define NBLK ((SCAN_N + 1023) / 1024)

// ---------------- scratch (device globals; no allocation) ----------------
__device__ int   g_cnt[SCAN_N];
__device__ int   g_off[SCAN_N + 1];
__device__ int   g_cur[SCAN_N];
__device__ int   g_bsum[NBLK];
__device__ int   g_esrc[3 * EE];        // flat, global CSR positions
__device__ float g_dn[SCAN_N];
__device__ float g_x[NN * HH];          // raw1
__device__ float g_p1[6 * NN];
__device__ float g_z1[3][NN * HH];      // EPS*x + aggregation
__device__ float g_raw2[NN * DD2];
__device__ float g_p2[6 * NN];
__device__ float g_z2c[3][BB * DD2];
__device__ float g_final[BB * FF];

__device__ __forceinline__ float lrelu(float v) { return v >= 0.f ? v : NEGS * v; }

__device__ __forceinline__ unsigned tf32r(float x) {
    unsigned u; asm("cvt.rna.tf32.f32 %0, %1;" : "=r"(u) : "f"(x)); return u;
}

__device__ __forceinline__ void mma8(float* d, unsigned a0, unsigned a1, unsigned a2, unsigned a3,
                                     unsigned b0, unsigned b1) {
    asm volatile("mma.sync.aligned.m16n8k8.row.col.f32.tf32.tf32.f32 "
                 "{%0,%1,%2,%3}, {%4,%5,%6,%7}, {%8,%9}, {%0,%1,%2,%3};"
                 : "+f"(d[0]), "+f"(d[1]), "+f"(d[2]), "+f"(d[3])
                 : "r"(a0), "r"(a1), "r"(a2), "r"(a3), "r"(b0), "r"(b1));
}

// ---------------- init / degree ----------------
__global__ void k_init() {
    int i = blockIdx.x * 256 + threadIdx.x;
    if (i < SCAN_N) g_cnt[i] = 0;
}

__global__ void k_hist(const int* __restrict__ d0, const int* __restrict__ d1,
                       const int* __restrict__ d2) {
    int set = blockIdx.y;
    int e = blockIdx.x * 256 + threadIdx.x;
    const int* d = set == 0 ? d0 : (set == 1 ? d1 : d2);
    atomicAdd(&g_cnt[set * NN + d[e]], 1);
}

// ---------------- parallel 2-kernel scan (dn folded into phase 1) ----------------
__global__ void k_scan_local() {
    int tid = threadIdx.x, lane = tid & 31, wid = tid >> 5;
    __shared__ int wsum[32];
    int i = blockIdx.x * 1024 + tid;
    int v = (i < SCAN_N) ? g_cnt[i] : 0;
    if (i < SCAN_N) g_dn[i] = v > 0 ? rsqrtf((float)v) : 0.f;
    int x = v;
#pragma unroll
    for (int o = 1; o < 32; o <<= 1) {
        int y = __shfl_up_sync(0xffffffffu, x, o);
        if (lane >= o) x += y;
    }
    if (lane == 31) wsum[wid] = x;
    __syncthreads();
    if (wid == 0) {
        int s = wsum[lane];
#pragma unroll
        for (int o = 1; o < 32; o <<= 1) {
            int y = __shfl_up_sync(0xffffffffu, s, o);
            if (lane >= o) s += y;
        }
        wsum[lane] = s;
    }
    __syncthreads();
    int excl = (wid ? wsum[wid - 1] : 0) + x - v;
    if (i < SCAN_N) g_off[i] = excl;
    if (tid == 1023) g_bsum[blockIdx.x] = wsum[31];
}

// adds prefix of g_bsum[0..bid) to this block's offsets
__global__ void k_scan_add() {
    int tid = threadIdx.x, lane = tid & 31, wid = tid >> 5;
    __shared__ int partial[32];
    __shared__ int s_off;
    int v = (tid < blockIdx.x) ? g_bsum[tid] : 0;
#pragma unroll
    for (int o = 16; o; o >>= 1) v += __shfl_down_sync(0xffffffffu, v, o);
    if (lane == 0) partial[wid] = v;
    __syncthreads();
    if (wid == 0) {
        int s = partial[lane];
#pragma unroll
        for (int o = 16; o; o >>= 1) s += __shfl_down_sync(0xffffffffu, s, o);
        if (lane == 0) s_off = s;
    }
    __syncthreads();
    int i = blockIdx.x * 1024 + tid;
    if (i < SCAN_N) {
        int o = g_off[i] + s_off;
        g_off[i] = o;
        g_cur[i] = o;
    }
    if (i == 0) g_off[SCAN_N] = 3 * EE;
}

__global__ void k_fill(const int* __restrict__ s0, const int* __restrict__ s1, const int* __restrict__ s2,
                       const int* __restrict__ d0, const int* __restrict__ d1, const int* __restrict__ d2) {
    int set = blockIdx.y;
    int e = blockIdx.x * 256 + threadIdx.x;
    const int* src = set == 0 ? s0 : (set == 1 ? s1 : s2);
    const int* dst = set == 0 ? d0 : (set == 1 ? d1 : d2);
    int dt = dst[e];
    int pos = atomicAdd(&g_cur[set * NN + dt], 1);
    g_esrc[pos] = src[e];
}

// ---------------- GEMM t1 via 3xTF32 mma + fused layer-1 gate projections ----------------
// x[128,64] = leaky(h[128,256] @ w[64,256]^T + b), per block.
// 4 warps x 32-row warp tiles (2 mma tiles/warp): each B fragment read feeds
// 6 mmas -> LDS per block halves vs 8x16 layout (was L1-bound at 70.8%).
__global__ __launch_bounds__(128, 4) void k_gemm_t1(const float* __restrict__ h,
                                                    const float* __restrict__ w_,
                                                    const float* __restrict__ bias,
                                                    const float* __restrict__ g0,
                                                    const float* __restrict__ g1,
                                                    const float* __restrict__ g2) {
    __shared__ union {
        float4 wf[8][64][4];   // per (kg,n,c): (hi_k, hi_k4, lo_k, lo_k4)
        float  xs[128][65];    // x tile for fused proj epilogue
    } sh;
    __shared__ float gsm[384];
    int tid = threadIdx.x, lane = tid & 31, wid = tid >> 5;   // wid 0..3
    int m0 = blockIdx.x * 128;
    int mw = m0 + wid * 32;
    int r = lane >> 2, c = lane & 3;
    float d[2][8][4] = {};

    for (int chunk = 0; chunk < 4; chunk++) {
        int kbase = chunk * 64;
        __syncthreads();
        // stage W chunk as hi/lo tf32 pairs, laid out for the B fragment
        for (int t = tid; t < 2048; t += 128) {
            int cc = t & 3, n = (t >> 2) & 63, kg = t >> 8;
            int k = kbase + kg * 8 + cc;
            float h0 = w_[n * INP + k], h4 = w_[n * INP + k + 4];
            unsigned u0 = tf32r(h0), u4 = tf32r(h4);
            float f0 = __uint_as_float(u0), f4 = __uint_as_float(u4);
            sh.wf[kg][n][cc] = make_float4(f0, f4,
                                           __uint_as_float(tf32r(h0 - f0)),
                                           __uint_as_float(tf32r(h4 - f4)));
        }
        __syncthreads();
        const float* hrA = h + (long)(mw + r) * INP;
        const float* hrB = h + (long)(mw + r + 8) * INP;
        const float* hrC = h + (long)(mw + 16 + r) * INP;
        const float* hrD = h + (long)(mw + 16 + r + 8) * INP;
        bool okA = (mw + r) < NN,      okB = (mw + r + 8) < NN;
        bool okC = (mw + 16 + r) < NN, okD = (mw + 16 + r + 8) < NN;
#pragma unroll
        for (int kg = 0; kg < 8; kg++) {
            int k = kbase + kg * 8 + c;
            // tile 0 fragments
            float a00 = okA ? hrA[k] : 0.f,     a10 = okB ? hrB[k] : 0.f;
            float a01 = okA ? hrA[k + 4] : 0.f, a11 = okB ? hrB[k + 4] : 0.f;
            unsigned p0 = tf32r(a00), p1 = tf32r(a10), p2 = tf32r(a01), p3 = tf32r(a11);
            unsigned q0 = tf32r(a00 - __uint_as_float(p0));
            unsigned q1 = tf32r(a10 - __uint_as_float(p1));
            unsigned q2 = tf32r(a01 - __uint_as_float(p2));
            unsigned q3 = tf32r(a11 - __uint_as_float(p3));
            // tile 1 fragments
            float b00 = okC ? hrC[k] : 0.f,     b10 = okD ? hrD[k] : 0.f;
            float b01 = okC ? hrC[k + 4] : 0.f, b11 = okD ? hrD[k + 4] : 0.f;
            unsigned s0 = tf32r(b00), s1 = tf32r(b10), s2 = tf32r(b01), s3 = tf32r(b11);
            unsigned t0 = tf32r(b00 - __uint_as_float(s0));
            unsigned t1 = tf32r(b10 - __uint_as_float(s1));
            unsigned t2 = tf32r(b01 - __uint_as_float(s2));
            unsigned t3 = tf32r(b11 - __uint_as_float(s3));
#pragma unroll
            for (int j = 0; j < 8; j++) {
                float4 b = sh.wf[kg][j * 8 + r][c];
                unsigned bh0 = __float_as_uint(b.x), bh1 = __float_as_uint(b.y);
                unsigned bl0 = __float_as_uint(b.z), bl1 = __float_as_uint(b.w);
                mma8(d[0][j], p0, p1, p2, p3, bh0, bh1);
                mma8(d[0][j], p0, p1, p2, p3, bl0, bl1);
                mma8(d[0][j], q0, q1, q2, q3, bh0, bh1);
                mma8(d[1][j], s0, s1, s2, s3, bh0, bh1);
                mma8(d[1][j], s0, s1, s2, s3, bl0, bl1);
                mma8(d[1][j], t0, t1, t2, t3, bh0, bh1);
            }
        }
    }
    __syncthreads();   // all warps done reading wf before xs (aliased) is written

    // epilogue: bias + lrelu, write g_x and stash tile in xs
    {
        int c2 = c * 2;
#pragma unroll
        for (int tile = 0; tile < 2; tile++) {
            int row0 = mw + tile * 16 + r, row1 = row0 + 8;
            int lr0 = wid * 32 + tile * 16 + r, lr1 = lr0 + 8;
#pragma unroll
            for (int j = 0; j < 8; j++) {
                int col = j * 8 + c2;
                float b0 = bias[col], b1 = bias[col + 1];
                float v00 = lrelu(d[tile][j][0] + b0);
                float v01 = lrelu(d[tile][j][1] + b1);
                float v10 = lrelu(d[tile][j][2] + b0);
                float v11 = lrelu(d[tile][j][3] + b1);
                sh.xs[lr0][col] = v00; sh.xs[lr0][col + 1] = v01;
                sh.xs[lr1][col] = v10; sh.xs[lr1][col + 1] = v11;
                if (row0 < NN) { g_x[row0 * HH + col] = v00; g_x[row0 * HH + col + 1] = v01; }
                if (row1 < NN) { g_x[row1 * HH + col] = v10; g_x[row1 * HH + col + 1] = v11; }
            }
        }
    }
    for (int t = tid; t < 384; t += 128) {
        int cb = t >> 6, k = t & 63;
        const float* gw = (cb >> 1) == 0 ? g0 : ((cb >> 1) == 1 ? g1 : g2);
        gsm[t] = gw[(cb & 1) * 64 + k];
    }
    __syncthreads();
    // 768 dots: 128 rows x 6 combos
    for (int t2 = tid; t2 < 768; t2 += 128) {
        int rr = t2 & 127, cb = t2 >> 7;
        int n = m0 + rr;
        if (n < NN) {
            const float* xr = &sh.xs[rr][0];
            const float* gr = &gsm[cb * 64];
            float sum = 0.f;
#pragma unroll
            for (int k = 0; k < 64; k++) sum += xr[k] * gr[k];
            g_p1[cb * NN + n] = sum;
        }
    }
}

// ---------------- layer-1 aggregation: warp per dst node ----------------
__global__ void k_agg1(const float* __restrict__ b0, const float* __restrict__ b1,
                       const float* __restrict__ b2) {
    int set = blockIdx.y;
    int n = blockIdx.x * 8 + (threadIdx.x >> 5);
    if (n >= NN) return;
    int lane = threadIdx.x & 31;
    const float* gb = set == 0 ? b0 : (set == 1 ? b1 : b2);
    int start = g_off[set * NN + n];
    int end = g_off[set * NN + n + 1];
    float dnn = g_dn[set * NN + n];
    float pdn = g_p1[(set * 2 + 0) * NN + n] + gb[0];
    float acc0 = 0.f, acc1 = 0.f;
    for (int p = start; p < end; p += 32) {
        int j = p + lane;
        int sj = 0; float tj = 0.f;
        if (j < end) {
            sj = g_esrc[j];
            float a = tanhf(pdn + g_p1[(set * 2 + 1) * NN + sj]);
            tj = a * dnn * g_dn[set * NN + sj];
        }
        int cnt = min(32, end - p);
#pragma unroll 4
        for (int q = 0; q < cnt; q++) {
            int s = __shfl_sync(0xffffffffu, sj, q);
            float t = __shfl_sync(0xffffffffu, tj, q);
            float2 v = ((const float2*)g_x)[s * 32 + lane];
            acc0 += t * v.x; acc1 += t * v.y;
        }
    }
    float2 xv = ((const float2*)g_x)[n * 32 + lane];
    float2 o;
    o.x = EPSC * xv.x + acc0;
    o.y = EPSC * xv.y + acc1;
    ((float2*)g_z1[set])[n * 32 + lane] = o;
}

// ---------------- GEMM h1_i = leaky(z1 @ hw1_i) via 3xTF32 mma ----------------
// out[128,64] per block; K=64 single staged chunk; B[n][k] = hw[k*64+n].
__global__ __launch_bounds__(128, 4) void k_gemm_h1(const float* __restrict__ w0,
                                                    const float* __restrict__ w1,
                                                    const float* __restrict__ w2) {
    int set = blockIdx.y;
    const float* hw = set == 0 ? w0 : (set == 1 ? w1 : w2);
    __shared__ float4 wf[8][64][4];
    int tid = threadIdx.x, lane = tid & 31, wid = tid >> 5;
    int m0 = blockIdx.x * 128;
    int mw = m0 + wid * 32;
    int r = lane >> 2, c = lane & 3;
    float d[2][8][4] = {};

    for (int t = tid; t < 2048; t += 128) {
        int cc = t & 3, n = (t >> 2) & 63, kg = t >> 8;
        int k = kg * 8 + cc;
        float h0 = hw[k * HH + n], h4 = hw[(k + 4) * HH + n];
        unsigned u0 = tf32r(h0), u4 = tf32r(h4);
        float f0 = __uint_as_float(u0), f4 = __uint_as_float(u4);
        wf[kg][n][cc] = make_float4(f0, f4,
                                    __uint_as_float(tf32r(h0 - f0)),
                                    __uint_as_float(tf32r(h4 - f4)));
    }
    __syncthreads();
    const float* z = g_z1[set];
    const float* hrA = z + (long)(mw + r) * HH;
    const float* hrB = z + (long)(mw + r + 8) * HH;
    const float* hrC = z + (long)(mw + 16 + r) * HH;
    const float* hrD = z + (long)(mw + 16 + r + 8) * HH;
    bool okA = (mw + r) < NN,      okB = (mw + r + 8) < NN;
    bool okC = (mw + 16 + r) < NN, okD = (mw + 16 + r + 8) < NN;
#pragma unroll
    for (int kg = 0; kg < 8; kg++) {
        int k = kg * 8 + c;
        float a00 = okA ? hrA[k] : 0.f,     a10 = okB ? hrB[k] : 0.f;
        float a01 = okA ? hrA[k + 4] : 0.f, a11 = okB ? hrB[k + 4] : 0.f;
        unsigned p0 = tf32r(a00), p1 = tf32r(a10), p2 = tf32r(a01), p3 = tf32r(a11);
        unsigned q0 = tf32r(a00 - __uint_as_float(p0));
        unsigned q1 = tf32r(a10 - __uint_as_float(p1));
        unsigned q2 = tf32r(a01 - __uint_as_float(p2));
        unsigned q3 = tf32r(a11 - __uint_as_float(p3));
        float b00 = okC ? hrC[k] : 0.f,     b10 = okD ? hrD[k] : 0.f;
        float b01 = okC ? hrC[k + 4] : 0.f, b11 = okD ? hrD[k + 4] : 0.f;
        unsigned s0 = tf32r(b00), s1 = tf32r(b10), s2 = tf32r(b01), s3 = tf32r(b11);
        unsigned t0 = tf32r(b00 - __uint_as_float(s0));
        unsigned t1 = tf32r(b10 - __uint_as_float(s1));
        unsigned t2 = tf32r(b01 - __uint_as_float(s2));
        unsigned t3 = tf32r(b11 - __uint_as_float(s3));
#pragma unroll
        for (int j = 0; j < 8; j++) {
            float4 b = wf[kg][j * 8 + r][c];
            unsigned bh0 = __float_as_uint(b.x), bh1 = __float_as_uint(b.y);
            unsigned bl0 = __float_as_uint(b.z), bl1 = __float_as_uint(b.w);
            mma8(d[0][j], p0, p1, p2, p3, bh0, bh1);
            mma8(d[0][j], p0, p1, p2, p3, bl0, bl1);
            mma8(d[0][j], q0, q1, q2, q3, bh0, bh1);
            mma8(d[1][j], s0, s1, s2, s3, bh0, bh1);
            mma8(d[1][j], s0, s1, s2, s3, bl0, bl1);
            mma8(d[1][j], t0, t1, t2, t3, bh0, bh1);
        }
    }
    // epilogue: lrelu -> raw2 slice
    int c2 = c * 2;
#pragma unroll
    for (int tile = 0; tile < 2; tile++) {
        int row0 = mw + tile * 16 + r, row1 = row0 + 8;
#pragma unroll
        for (int j = 0; j < 8; j++) {
            int col = set * HH + j * 8 + c2;
            if (row0 < NN) {
                g_raw2[row0 * DD2 + col]     = lrelu(d[tile][j][0]);
                g_raw2[row0 * DD2 + col + 1] = lrelu(d[tile][j][1]);
            }
            if (row1 < NN) {
                g_raw2[row1 * DD2 + col]     = lrelu(d[tile][j][2]);
                g_raw2[row1 * DD2 + col + 1] = lrelu(d[tile][j][3]);
            }
        }
    }
}

// ---------------- per-node gate projections, layer 2 (D=192) ----------------
__global__ void k_proj2(const float* __restrict__ g0, const float* __restrict__ g1,
                        const float* __restrict__ g2) {
    int gt = blockIdx.x * 256 + threadIdx.x;
    int n = gt >> 5, lane = gt & 31;
    if (n >= NN) return;
    float r[6];
#pragma unroll
    for (int j = 0; j < 6; j++) r[j] = g_raw2[n * DD2 + lane + 32 * j];
    const float* gws[3] = {g0, g1, g2};
#pragma unroll
    for (int s = 0; s < 3; s++) {
        const float* gw = gws[s];
        float p = 0.f, q = 0.f;
#pragma unroll
        for (int j = 0; j < 6; j++) {
            p += r[j] * gw[lane + 32 * j];
            q += r[j] * gw[DD2 + lane + 32 * j];
        }
#pragma unroll
        for (int o = 16; o; o >>= 1) {
            p += __shfl_down_sync(0xffffffffu, p, o);
            q += __shfl_down_sync(0xffffffffu, q, o);
        }
        if (lane == 0) {
            g_p2[(s * 2 + 0) * NN + n] = p;
            g_p2[(s * 2 + 1) * NN + n] = q;
        }
    }
}

// ---------------- layer-2 aggregation: warp per selected slot ----------------
__global__ void k_agg2(const int* __restrict__ nodes, const float* __restrict__ b0,
                       const float* __restrict__ b1, const float* __restrict__ b2) {
    int set = blockIdx.y;
    int b = blockIdx.x * 8 + (threadIdx.x >> 5);
    int lane = threadIdx.x & 31;
    const float* gb = set == 0 ? b0 : (set == 1 ? b1 : b2);
    int n = nodes[b];
    int start = g_off[set * NN + n];
    int end = g_off[set * NN + n + 1];
    float dnn = g_dn[set * NN + n];
    float pdn = g_p2[(set * 2 + 0) * NN + n] + gb[0];
    float acc[6] = {};
    for (int p = start; p < end; p += 32) {
        int j = p + lane;
        int sj = 0; float tj = 0.f;
        if (j < end) {
            sj = g_esrc[j];
            float a = tanhf(pdn + g_p2[(set * 2 + 1) * NN + sj]);
            tj = a * dnn * g_dn[set * NN + sj];
        }
        int cnt = min(32, end - p);
#pragma unroll 2
        for (int q = 0; q < cnt; q++) {
            int s = __shfl_sync(0xffffffffu, sj, q);
            float t = __shfl_sync(0xffffffffu, tj, q);
            const float2* rp = ((const float2*)g_raw2) + (long)s * 96;
#pragma unroll
            for (int k = 0; k < 3; k++) {
                float2 v = rp[lane + 32 * k];
                acc[2 * k + 0] += t * v.x;
                acc[2 * k + 1] += t * v.y;
            }
        }
    }
    const float2* rn = ((const float2*)g_raw2) + (long)n * 96;
    float2* zp = ((float2*)g_z2c[set]) + (long)b * 96;
#pragma unroll
    for (int k = 0; k < 3; k++) {
        float2 v = rn[lane + 32 * k];
        float2 o;
        o.x = EPSC * v.x + acc[2 * k + 0];
        o.y = EPSC * v.y + acc[2 * k + 1];
        zp[lane + 32 * k] = o;
    }
}

// ---------------- build final cols 192..704 ----------------
__global__ void k_build_final(const int* __restrict__ nodes, const float* __restrict__ h) {
    int idx = blockIdx.x * 256 + threadIdx.x;
    if (idx >= BB * 512) return;
    int b = idx >> 9, c = idx & 511;
    int node = nodes[b];
    float v;
    if (c < 256) v = h[(long)node * INP + c];
    else if (c < 320) v = g_x[node * HH + (c - 256)];
    else v = g_raw2[node * DD2 + (c - 320)];
    g_final[b * FF + 192 + c] = v;
}

// ---------------- GEMM h2_i over B=4096 rows ----------------
__global__ void k_gemm_h2(const float* __restrict__ w0, const float* __restrict__ w1,
                          const float* __restrict__ w2) {
    int set = blockIdx.y;
    const float* hw = set == 0 ? w0 : (set == 1 ? w1 : w2);
    __shared__ float as[64][64];
    __shared__ float ws[64][68];
    int tid = threadIdx.x;
    int n0 = blockIdx.x * 64;
    int rg = tid >> 4, cg = tid & 15;
    float acc[4][4] = {};
    for (int kc = 0; kc < 3; kc++) {
        int k0 = kc * 64;
#pragma unroll
        for (int t = 0; t < 16; t++) {
            int i = tid + t * 256; int r = i >> 6, k = i & 63;
            as[r][k] = g_z2c[set][(n0 + r) * DD2 + k0 + k];
        }
#pragma unroll
        for (int t = 0; t < 16; t++) {
            int i = tid + t * 256; int k = i >> 6, j = i & 63;
            ws[k][j] = hw[(k0 + k) * HH + j];
        }
        __syncthreads();
#pragma unroll
        for (int k = 0; k < 64; k++) {
            float a0 = as[rg * 4 + 0][k], a1 = as[rg * 4 + 1][k];
            float a2 = as[rg * 4 + 2][k], a3 = as[rg * 4 + 3][k];
            float4 b4 = *(const float4*)&ws[k][cg * 4];
            acc[0][0] += a0 * b4.x; acc[0][1] += a0 * b4.y; acc[0][2] += a0 * b4.z; acc[0][3] += a0 * b4.w;
            acc[1][0] += a1 * b4.x; acc[1][1] += a1 * b4.y; acc[1][2] += a1 * b4.z; acc[1][3] += a1 * b4.w;
            acc[2][0] += a2 * b4.x; acc[2][1] += a2 * b4.y; acc[2][2] += a2 * b4.z; acc[2][3] += a2 * b4.w;
            acc[3][0] += a3 * b4.x; acc[3][1] += a3 * b4.y; acc[3][2] += a3 * b4.z; acc[3][3] += a3 * b4.w;
        }
        __syncthreads();
    }
#pragma unroll
    for (int i = 0; i < 4; i++) {
        int b = n0 + rg * 4 + i;
#pragma unroll
        for (int j = 0; j < 4; j++)
            g_final[b * FF + set * HH + cg * 4 + j] = lrelu(acc[i][j]);
    }
}

// ---------------- GEMM s64 = leaky(final @ t2_w^T + b) ----------------
__global__ void k_gemm_t2(const float* __restrict__ w, const float* __restrict__ bias,
                          float* __restrict__ s64) {
    __shared__ float as[64][64];
    __shared__ float ws[64][68];
    int tid = threadIdx.x;
    int n0 = blockIdx.x * 64;
    int rg = tid >> 4, cg = tid & 15;
    float acc[4][4] = {};
    for (int kc = 0; kc < 11; kc++) {
        int k0 = kc * 64;
#pragma unroll
        for (int t = 0; t < 16; t++) {
            int i = tid + t * 256; int r = i >> 6, k = i & 63;
            as[r][k] = g_final[(n0 + r) * FF + k0 + k];
        }
#pragma unroll
        for (int t = 0; t < 16; t++) {
            int i = tid + t * 256; int j = i >> 6, k = i & 63;
            ws[k][j] = w[j * FF + k0 + k];
        }
        __syncthreads();
#pragma unroll
        for (int k = 0; k < 64; k++) {
            float a0 = as[rg * 4 + 0][k], a1 = as[rg * 4 + 1][k];
            float a2 = as[rg * 4 + 2][k], a3 = as[rg * 4 + 3][k];
            float4 b4 = *(const float4*)&ws[k][cg * 4];
            acc[0][0] += a0 * b4.x; acc[0][1] += a0 * b4.y; acc[0][2] += a0 * b4.z; acc[0][3] += a0 * b4.w;
            acc[1][0] += a1 * b4.x; acc[1][1] += a1 * b4.y; acc[1][2] += a1 * b4.z; acc[1][3] += a1 * b4.w;
            acc[2][0] += a2 * b4.x; acc[2][1] += a2 * b4.y; acc[2][2] += a2 * b4.z; acc[2][3] += a2 * b4.w;
            acc[3][0] += a3 * b4.x; acc[3][1] += a3 * b4.y; acc[3][2] += a3 * b4.z; acc[3][3] += a3 * b4.w;
        }
        __syncthreads();
    }
#pragma unroll
    for (int i = 0; i < 4; i++) {
        int b = n0 + rg * 4 + i;
#pragma unroll
        for (int j = 0; j < 4; j++) {
            float v = acc[i][j] + bias[cg * 4 + j];
            s64[b * HH + cg * 4 + j] = lrelu(v);
        }
    }
}

// ---------------- scores = s64 @ t3_w^T + t3_b ----------------
__global__ void k_t3(const float* __restrict__ s64, const float* __restrict__ w,
                     const float* __restrict__ bias, float* __restrict__ scores) {
    int b = blockIdx.x * 256 + threadIdx.x;
    if (b >= BB) return;
    float a0 = bias[0], a1 = bias[1];
#pragma unroll 8
    for (int k = 0; k < 64; k++) {
        float v = s64[b * HH + k];
        a0 += v * __ldg(&w[k]);
        a1 += v * __ldg(&w[64 + k]);
    }
    scores[b * 2 + 0] = a0;
    scores[b * 2 + 1] = a1;
}

// ---------------- host ----------------
extern "C" void kernel_launch(void* const* d_in, const int* in_sizes, int n_in,
                              void* d_out, int out_size) {
    const float *h, *t1w, *t1b, *t2w, *t2b, *t3w, *t3b;
    const float *gw1[3], *gb1[3], *hw1[3], *gw2[3], *gb2[3], *hw2[3];
    const int *src[3], *dst[3], *nodes;

    if (in_sizes[1] == EE) {
        h = (const float*)d_in[0];
        src[0] = (const int*)d_in[1]; dst[0] = (const int*)d_in[2];
        src[1] = (const int*)d_in[3]; dst[1] = (const int*)d_in[4];
        src[2] = (const int*)d_in[5]; dst[2] = (const int*)d_in[6];
        nodes = (const int*)d_in[7];
        t1w = (const float*)d_in[8]; t1b = (const float*)d_in[9];
        for (int i = 0; i < 3; i++) {
            gw1[i] = (const float*)d_in[10 + 6 * i];
            gb1[i] = (const float*)d_in[11 + 6 * i];
            hw1[i] = (const float*)d_in[12 + 6 * i];
            gw2[i] = (const float*)d_in[13 + 6 * i];
            gb2[i] = (const float*)d_in[14 + 6 * i];
            hw2[i] = (const float*)d_in[15 + 6 * i];
        }
        t2w = (const float*)d_in[28]; t2b = (const float*)d_in[29];
        t3w = (const float*)d_in[30]; t3b = (const float*)d_in[31];
    } else {
        h = (const float*)d_in[0];
        t1w = (const float*)d_in[1]; t1b = (const float*)d_in[2];
        for (int i = 0; i < 3; i++) {
            gw1[i] = (const float*)d_in[3 + 3 * i];
            gb1[i] = (const float*)d_in[4 + 3 * i];
            hw1[i] = (const float*)d_in[5 + 3 * i];
            gw2[i] = (const float*)d_in[12 + 3 * i];
            gb2[i] = (const float*)d_in[13 + 3 * i];
            hw2[i] = (const float*)d_in[14 + 3 * i];
        }
        t2w = (const float*)d_in[21]; t2b = (const float*)d_in[22];
        t3w = (const float*)d_in[23]; t3b = (const float*)d_in[24];
        src[0] = (const int*)d_in[25]; dst[0] = (const int*)d_in[26];
        src[1] = (const int*)d_in[27]; dst[1] = (const int*)d_in[28];
        src[2] = (const int*)d_in[29]; dst[2] = (const int*)d_in[30];
        nodes = (const int*)d_in[31];
    }

    float* out = (float*)d_out;
    float* scores = out;
    float* s64 = out + BB * 2;

    // CSR build + t1 GEMM
    k_init<<<(SCAN_N + 255) / 256, 256>>>();
    k_hist<<<dim3(EE / 256, 3), 256>>>(dst[0], dst[1], dst[2]);
    k_scan_local<<<NBLK, 1024>>>();
    k_gemm_t1<<<(NN + 127) / 128, 128>>>(h, t1w, t1b, gw1[0], gw1[1], gw1[2]);
    k_scan_add<<<NBLK, 1024>>>();
    k_fill<<<dim3(EE / 256, 3), 256>>>(src[0], src[1], src[2], dst[0], dst[1], dst[2]);
    // layer 1
    k_agg1<<<dim3((NN + 7) / 8, 3), 256>>>(gb1[0], gb1[1], gb1[2]);
    k_gemm_h1<<<dim3((NN + 127) / 128, 3), 128>>>(hw1[0], hw1[1], hw1[2]);
    // layer 2 (selected dst only)
    k_proj2<<<(NN * 32 + 255) / 256, 256>>>(gw2[0], gw2[1], gw2[2]);
    k_agg2<<<dim3(BB / 8, 3), 256>>>(nodes, gb2[0], gb2[1], gb2[2]);
    // readout
    k_build_final<<<(BB * 512 + 255) / 256, 256>>>(nodes, h);
    k_gemm_h2<<<dim3(BB / 64, 3), 256>>>(hw2[0], hw2[1], hw2[2]);
    k_gemm_t2<<<BB / 64, 256>>>(t2w, t2b, s64);
    k_t3<<<(BB + 255) / 256, 256>>>(s64, t3w, t3b, scores);
}

// round 17
// speedup vs baseline: 1.0452x; 1.0452x over previous
#include <cuda_runtime.h>

#define NN 50000
#define EE 800000
#define INP 256
#define HH 64
#define BB 4096
#define DD2 192
#define FF 704
#define EPSC 0.3f
#define NEGS 0.3f
#define SCAN_N (3 * NN)
#define NBLK ((SCAN_N + 1023) / 1024)
#define E4 (EE / 4)

// ---------------- scratch (device globals; no allocation) ----------------
__device__ int   g_cnt[SCAN_N];
__device__ int   g_off[SCAN_N + 1];
__device__ int   g_cur[SCAN_N];
__device__ int   g_bsum[NBLK];
__device__ int   g_esrc[3 * EE];        // flat, global CSR positions
__device__ float g_dn[SCAN_N];
__device__ float g_x[NN * HH];          // raw1
__device__ float g_p1[6 * NN];
__device__ float g_z1[3][NN * HH];      // EPS*x + aggregation
__device__ float g_raw2[NN * DD2];
__device__ float g_p2[6 * NN];
__device__ float g_z2c[3][BB * DD2];
__device__ float g_final[BB * FF];

__device__ __forceinline__ float lrelu(float v) { return v >= 0.f ? v : NEGS * v; }

__device__ __forceinline__ unsigned tf32r(float x) {
    unsigned u; asm("cvt.rna.tf32.f32 %0, %1;" : "=r"(u) : "f"(x)); return u;
}

__device__ __forceinline__ void mma8(float* d, unsigned a0, unsigned a1, unsigned a2, unsigned a3,
                                     unsigned b0, unsigned b1) {
    asm volatile("mma.sync.aligned.m16n8k8.row.col.f32.tf32.tf32.f32 "
                 "{%0,%1,%2,%3}, {%4,%5,%6,%7}, {%8,%9}, {%0,%1,%2,%3};"
                 : "+f"(d[0]), "+f"(d[1]), "+f"(d[2]), "+f"(d[3])
                 : "r"(a0), "r"(a1), "r"(a2), "r"(a3), "r"(b0), "r"(b1));
}

// ---------------- degree histogram (4 edges per thread via int4, guarded) ----------------
__global__ void k_hist(const int* __restrict__ d0, const int* __restrict__ d1,
                       const int* __restrict__ d2) {
    int set = blockIdx.y;
    int e4 = blockIdx.x * 256 + threadIdx.x;
    if (e4 >= E4) return;                       // FIX: cover all EE edges
    const int* d = set == 0 ? d0 : (set == 1 ? d1 : d2);
    int4 v = ((const int4*)d)[e4];
    int base = set * NN;
    atomicAdd(&g_cnt[base + v.x], 1);
    atomicAdd(&g_cnt[base + v.y], 1);
    atomicAdd(&g_cnt[base + v.z], 1);
    atomicAdd(&g_cnt[base + v.w], 1);
}

// ---------------- parallel 2-kernel scan (dn folded into phase 1) ----------------
__global__ void k_scan_local() {
    int tid = threadIdx.x, lane = tid & 31, wid = tid >> 5;
    __shared__ int wsum[32];
    int i = blockIdx.x * 1024 + tid;
    int v = (i < SCAN_N) ? g_cnt[i] : 0;
    if (i < SCAN_N) g_dn[i] = v > 0 ? rsqrtf((float)v) : 0.f;
    int x = v;
#pragma unroll
    for (int o = 1; o < 32; o <<= 1) {
        int y = __shfl_up_sync(0xffffffffu, x, o);
        if (lane >= o) x += y;
    }
    if (lane == 31) wsum[wid] = x;
    __syncthreads();
    if (wid == 0) {
        int s = wsum[lane];
#pragma unroll
        for (int o = 1; o < 32; o <<= 1) {
            int y = __shfl_up_sync(0xffffffffu, s, o);
            if (lane >= o) s += y;
        }
        wsum[lane] = s;
    }
    __syncthreads();
    int excl = (wid ? wsum[wid - 1] : 0) + x - v;
    if (i < SCAN_N) g_off[i] = excl;
    if (tid == 1023) g_bsum[blockIdx.x] = wsum[31];
}

// adds prefix of g_bsum[0..bid) to this block's offsets
__global__ void k_scan_add() {
    int tid = threadIdx.x, lane = tid & 31, wid = tid >> 5;
    __shared__ int partial[32];
    __shared__ int s_off;
    int v = (tid < blockIdx.x) ? g_bsum[tid] : 0;
#pragma unroll
    for (int o = 16; o; o >>= 1) v += __shfl_down_sync(0xffffffffu, v, o);
    if (lane == 0) partial[wid] = v;
    __syncthreads();
    if (wid == 0) {
        int s = partial[lane];
#pragma unroll
        for (int o = 16; o; o >>= 1) s += __shfl_down_sync(0xffffffffu, s, o);
        if (lane == 0) s_off = s;
    }
    __syncthreads();
    int i = blockIdx.x * 1024 + tid;
    if (i < SCAN_N) {
        int o = g_off[i] + s_off;
        g_off[i] = o;
        g_cur[i] = o;
    }
    if (i == 0) g_off[SCAN_N] = 3 * EE;
}

__global__ void k_fill(const int* __restrict__ s0, const int* __restrict__ s1, const int* __restrict__ s2,
                       const int* __restrict__ d0, const int* __restrict__ d1, const int* __restrict__ d2) {
    int set = blockIdx.y;
    int e = blockIdx.x * 256 + threadIdx.x;
    const int* src = set == 0 ? s0 : (set == 1 ? s1 : s2);
    const int* dst = set == 0 ? d0 : (set == 1 ? d1 : d2);
    int dt = dst[e];
    int pos = atomicAdd(&g_cur[set * NN + dt], 1);
    g_esrc[pos] = src[e];
}

// ---------------- GEMM t1 via 3xTF32 mma + fused layer-1 gate projections ----------------
// x[128,64] = leaky(h[128,256] @ w[64,256]^T + b), per block.  (proven R13 shape)
__global__ __launch_bounds__(256, 3) void k_gemm_t1(const float* __restrict__ h,
                                                    const float* __restrict__ w_,
                                                    const float* __restrict__ bias,
                                                    const float* __restrict__ g0,
                                                    const float* __restrict__ g1,
                                                    const float* __restrict__ g2) {
    __shared__ union {
        float4 wf[8][64][4];   // per (kg,n,c): (hi_k, hi_k4, lo_k, lo_k4)
        float  xs[128][65];    // x tile for fused proj epilogue
    } sh;
    __shared__ float gsm[384];
    int tid = threadIdx.x, lane = tid & 31, wid = tid >> 5;
    int m0 = blockIdx.x * 128;
    int mw = m0 + wid * 16;
    int r = lane >> 2, c = lane & 3;
    float d[8][4] = {};

    for (int chunk = 0; chunk < 4; chunk++) {
        int kbase = chunk * 64;
        __syncthreads();
        for (int t = tid; t < 2048; t += 256) {
            int cc = t & 3, n = (t >> 2) & 63, kg = t >> 8;
            int k = kbase + kg * 8 + cc;
            float h0 = w_[n * INP + k], h4 = w_[n * INP + k + 4];
            unsigned u0 = tf32r(h0), u4 = tf32r(h4);
            float f0 = __uint_as_float(u0), f4 = __uint_as_float(u4);
            sh.wf[kg][n][cc] = make_float4(f0, f4,
                                           __uint_as_float(tf32r(h0 - f0)),
                                           __uint_as_float(tf32r(h4 - f4)));
        }
        __syncthreads();
        const float* hr0 = h + (long)(mw + r) * INP;
        const float* hr1 = h + (long)(mw + r + 8) * INP;
        bool ok0 = (mw + r) < NN, ok1 = (mw + r + 8) < NN;
#pragma unroll
        for (int kg = 0; kg < 8; kg++) {
            int k = kbase + kg * 8 + c;
            float a00 = ok0 ? hr0[k] : 0.f;
            float a10 = ok1 ? hr1[k] : 0.f;
            float a01 = ok0 ? hr0[k + 4] : 0.f;
            float a11 = ok1 ? hr1[k + 4] : 0.f;
            unsigned ah0 = tf32r(a00), ah1 = tf32r(a10), ah2 = tf32r(a01), ah3 = tf32r(a11);
            unsigned al0 = tf32r(a00 - __uint_as_float(ah0));
            unsigned al1 = tf32r(a10 - __uint_as_float(ah1));
            unsigned al2 = tf32r(a01 - __uint_as_float(ah2));
            unsigned al3 = tf32r(a11 - __uint_as_float(ah3));
#pragma unroll
            for (int j = 0; j < 8; j++) {
                float4 b = sh.wf[kg][j * 8 + r][c];
                unsigned bh0 = __float_as_uint(b.x), bh1 = __float_as_uint(b.y);
                unsigned bl0 = __float_as_uint(b.z), bl1 = __float_as_uint(b.w);
                mma8(d[j], ah0, ah1, ah2, ah3, bh0, bh1);
                mma8(d[j], ah0, ah1, ah2, ah3, bl0, bl1);
                mma8(d[j], al0, al1, al2, al3, bh0, bh1);
            }
        }
    }
    __syncthreads();

    {
        int c2 = c * 2;
        int row0 = mw + r, row1 = mw + r + 8;
        int lr0 = wid * 16 + r, lr1 = lr0 + 8;
#pragma unroll
        for (int j = 0; j < 8; j++) {
            int col = j * 8 + c2;
            float b0 = bias[col], b1 = bias[col + 1];
            float v00 = lrelu(d[j][0] + b0);
            float v01 = lrelu(d[j][1] + b1);
            float v10 = lrelu(d[j][2] + b0);
            float v11 = lrelu(d[j][3] + b1);
            sh.xs[lr0][col] = v00; sh.xs[lr0][col + 1] = v01;
            sh.xs[lr1][col] = v10; sh.xs[lr1][col + 1] = v11;
            if (row0 < NN) { g_x[row0 * HH + col] = v00; g_x[row0 * HH + col + 1] = v01; }
            if (row1 < NN) { g_x[row1 * HH + col] = v10; g_x[row1 * HH + col + 1] = v11; }
        }
    }
    for (int t = tid; t < 384; t += 256) {
        int cb = t >> 6, k = t & 63;
        const float* gw = (cb >> 1) == 0 ? g0 : ((cb >> 1) == 1 ? g1 : g2);
        gsm[t] = gw[(cb & 1) * 64 + k];
    }
    __syncthreads();
    for (int t2 = tid; t2 < 768; t2 += 256) {
        int rr = t2 & 127, cb = t2 >> 7;
        int n = m0 + rr;
        if (n < NN) {
            const float* xr = &sh.xs[rr][0];
            const float* gr = &gsm[cb * 64];
            float sum = 0.f;
#pragma unroll
            for (int k = 0; k < 64; k++) sum += xr[k] * gr[k];
            g_p1[cb * NN + n] = sum;
        }
    }
}

// ---------------- layer-1 aggregation: warp per dst node ----------------
__global__ void k_agg1(const float* __restrict__ b0, const float* __restrict__ b1,
                       const float* __restrict__ b2) {
    int set = blockIdx.y;
    int n = blockIdx.x * 8 + (threadIdx.x >> 5);
    if (n >= NN) return;
    int lane = threadIdx.x & 31;
    const float* gb = set == 0 ? b0 : (set == 1 ? b1 : b2);
    int start = g_off[set * NN + n];
    int end = g_off[set * NN + n + 1];
    float dnn = g_dn[set * NN + n];
    float pdn = g_p1[(set * 2 + 0) * NN + n] + gb[0];
    float acc0 = 0.f, acc1 = 0.f;
    for (int p = start; p < end; p += 32) {
        int j = p + lane;
        int sj = 0; float tj = 0.f;
        if (j < end) {
            sj = g_esrc[j];
            float a = tanhf(pdn + g_p1[(set * 2 + 1) * NN + sj]);
            tj = a * dnn * g_dn[set * NN + sj];
        }
        int cnt = min(32, end - p);
#pragma unroll 4
        for (int q = 0; q < cnt; q++) {
            int s = __shfl_sync(0xffffffffu, sj, q);
            float t = __shfl_sync(0xffffffffu, tj, q);
            float2 v = ((const float2*)g_x)[s * 32 + lane];
            acc0 += t * v.x; acc1 += t * v.y;
        }
    }
    float2 xv = ((const float2*)g_x)[n * 32 + lane];
    float2 o;
    o.x = EPSC * xv.x + acc0;
    o.y = EPSC * xv.y + acc1;
    ((float2*)g_z1[set])[n * 32 + lane] = o;
}

// ---------------- GEMM h1_i = leaky(z1 @ hw1_i) (proven 4x4 fp32) ----------------
__global__ void k_gemm_h1(const float* __restrict__ w0, const float* __restrict__ w1,
                          const float* __restrict__ w2) {
    int set = blockIdx.y;
    const float* hw = set == 0 ? w0 : (set == 1 ? w1 : w2);
    __shared__ float as[64][64];
    __shared__ float ws[64][68];
    int tid = threadIdx.x;
    int n0 = blockIdx.x * 64;
    int rg = tid >> 4, cg = tid & 15;
    float acc[4][4] = {};
#pragma unroll
    for (int t = 0; t < 16; t++) {
        int i = tid + t * 256; int r = i >> 6, k = i & 63;
        int n = n0 + r;
        as[r][k] = (n < NN) ? g_z1[set][n * HH + k] : 0.f;
    }
#pragma unroll
    for (int t = 0; t < 16; t++) {
        int i = tid + t * 256; int k = i >> 6, j = i & 63;
        ws[k][j] = hw[k * HH + j];
    }
    __syncthreads();
#pragma unroll
    for (int k = 0; k < 64; k++) {
        float a0 = as[rg * 4 + 0][k], a1 = as[rg * 4 + 1][k];
        float a2 = as[rg * 4 + 2][k], a3 = as[rg * 4 + 3][k];
        float4 b4 = *(const float4*)&ws[k][cg * 4];
        acc[0][0] += a0 * b4.x; acc[0][1] += a0 * b4.y; acc[0][2] += a0 * b4.z; acc[0][3] += a0 * b4.w;
        acc[1][0] += a1 * b4.x; acc[1][1] += a1 * b4.y; acc[1][2] += a1 * b4.z; acc[1][3] += a1 * b4.w;
        acc[2][0] += a2 * b4.x; acc[2][1] += a2 * b4.y; acc[2][2] += a2 * b4.z; acc[2][3] += a2 * b4.w;
        acc[3][0] += a3 * b4.x; acc[3][1] += a3 * b4.y; acc[3][2] += a3 * b4.z; acc[3][3] += a3 * b4.w;
    }
#pragma unroll
    for (int i = 0; i < 4; i++) {
        int n = n0 + rg * 4 + i; if (n >= NN) break;
#pragma unroll
        for (int j = 0; j < 4; j++)
            g_raw2[n * DD2 + set * HH + cg * 4 + j] = lrelu(acc[i][j]);
    }
}

// ---------------- per-node gate projections, layer 2 (D=192) ----------------
__global__ void k_proj2(const float* __restrict__ g0, const float* __restrict__ g1,
                        const float* __restrict__ g2) {
    int gt = blockIdx.x * 256 + threadIdx.x;
    int n = gt >> 5, lane = gt & 31;
    if (n >= NN) return;
    float r[6];
#pragma unroll
    for (int j = 0; j < 6; j++) r[j] = g_raw2[n * DD2 + lane + 32 * j];
    const float* gws[3] = {g0, g1, g2};
#pragma unroll
    for (int s = 0; s < 3; s++) {
        const float* gw = gws[s];
        float p = 0.f, q = 0.f;
#pragma unroll
        for (int j = 0; j < 6; j++) {
            p += r[j] * gw[lane + 32 * j];
            q += r[j] * gw[DD2 + lane + 32 * j];
        }
#pragma unroll
        for (int o = 16; o; o >>= 1) {
            p += __shfl_down_sync(0xffffffffu, p, o);
            q += __shfl_down_sync(0xffffffffu, q, o);
        }
        if (lane == 0) {
            g_p2[(s * 2 + 0) * NN + n] = p;
            g_p2[(s * 2 + 1) * NN + n] = q;
        }
    }
}

// ---------------- layer-2 aggregation: warp per selected slot ----------------
__global__ void k_agg2(const int* __restrict__ nodes, const float* __restrict__ b0,
                       const float* __restrict__ b1, const float* __restrict__ b2) {
    int set = blockIdx.y;
    int b = blockIdx.x * 8 + (threadIdx.x >> 5);
    int lane = threadIdx.x & 31;
    const float* gb = set == 0 ? b0 : (set == 1 ? b1 : b2);
    int n = nodes[b];
    int start = g_off[set * NN + n];
    int end = g_off[set * NN + n + 1];
    float dnn = g_dn[set * NN + n];
    float pdn = g_p2[(set * 2 + 0) * NN + n] + gb[0];
    float acc[6] = {};
    for (int p = start; p < end; p += 32) {
        int j = p + lane;
        int sj = 0; float tj = 0.f;
        if (j < end) {
            sj = g_esrc[j];
            float a = tanhf(pdn + g_p2[(set * 2 + 1) * NN + sj]);
            tj = a * dnn * g_dn[set * NN + sj];
        }
        int cnt = min(32, end - p);
#pragma unroll 2
        for (int q = 0; q < cnt; q++) {
            int s = __shfl_sync(0xffffffffu, sj, q);
            float t = __shfl_sync(0xffffffffu, tj, q);
            const float2* rp = ((const float2*)g_raw2) + (long)s * 96;
#pragma unroll
            for (int k = 0; k < 3; k++) {
                float2 v = rp[lane + 32 * k];
                acc[2 * k + 0] += t * v.x;
                acc[2 * k + 1] += t * v.y;
            }
        }
    }
    const float2* rn = ((const float2*)g_raw2) + (long)n * 96;
    float2* zp = ((float2*)g_z2c[set]) + (long)b * 96;
#pragma unroll
    for (int k = 0; k < 3; k++) {
        float2 v = rn[lane + 32 * k];
        float2 o;
        o.x = EPSC * v.x + acc[2 * k + 0];
        o.y = EPSC * v.y + acc[2 * k + 1];
        zp[lane + 32 * k] = o;
    }
}

// ---------------- build final cols 192..704 ----------------
__global__ void k_build_final(const int* __restrict__ nodes, const float* __restrict__ h) {
    int idx = blockIdx.x * 256 + threadIdx.x;
    if (idx >= BB * 512) return;
    int b = idx >> 9, c = idx & 511;
    int node = nodes[b];
    float v;
    if (c < 256) v = h[(long)node * INP + c];
    else if (c < 320) v = g_x[node * HH + (c - 256)];
    else v = g_raw2[node * DD2 + (c - 320)];
    g_final[b * FF + 192 + c] = v;
}

// ---------------- GEMM h2_i over B=4096 rows ----------------
__global__ void k_gemm_h2(const float* __restrict__ w0, const float* __restrict__ w1,
                          const float* __restrict__ w2) {
    int set = blockIdx.y;
    const float* hw = set == 0 ? w0 : (set == 1 ? w1 : w2);
    __shared__ float as[64][64];
    __shared__ float ws[64][68];
    int tid = threadIdx.x;
    int n0 = blockIdx.x * 64;
    int rg = tid >> 4, cg = tid & 15;
    float acc[4][4] = {};
    for (int kc = 0; kc < 3; kc++) {
        int k0 = kc * 64;
#pragma unroll
        for (int t = 0; t < 16; t++) {
            int i = tid + t * 256; int r = i >> 6, k = i & 63;
            as[r][k] = g_z2c[set][(n0 + r) * DD2 + k0 + k];
        }
#pragma unroll
        for (int t = 0; t < 16; t++) {
            int i = tid + t * 256; int k = i >> 6, j = i & 63;
            ws[k][j] = hw[(k0 + k) * HH + j];
        }
        __syncthreads();
#pragma unroll
        for (int k = 0; k < 64; k++) {
            float a0 = as[rg * 4 + 0][k], a1 = as[rg * 4 + 1][k];
            float a2 = as[rg * 4 + 2][k], a3 = as[rg * 4 + 3][k];
            float4 b4 = *(const float4*)&ws[k][cg * 4];
            acc[0][0] += a0 * b4.x; acc[0][1] += a0 * b4.y; acc[0][2] += a0 * b4.z; acc[0][3] += a0 * b4.w;
            acc[1][0] += a1 * b4.x; acc[1][1] += a1 * b4.y; acc[1][2] += a1 * b4.z; acc[1][3] += a1 * b4.w;
            acc[2][0] += a2 * b4.x; acc[2][1] += a2 * b4.y; acc[2][2] += a2 * b4.z; acc[2][3] += a2 * b4.w;
            acc[3][0] += a3 * b4.x; acc[3][1] += a3 * b4.y; acc[3][2] += a3 * b4.z; acc[3][3] += a3 * b4.w;
        }
        __syncthreads();
    }
#pragma unroll
    for (int i = 0; i < 4; i++) {
        int b = n0 + rg * 4 + i;
#pragma unroll
        for (int j = 0; j < 4; j++)
            g_final[b * FF + set * HH + cg * 4 + j] = lrelu(acc[i][j]);
    }
}

// ---------------- GEMM s64 = leaky(final @ t2_w^T + b) ----------------
__global__ void k_gemm_t2(const float* __restrict__ w, const float* __restrict__ bias,
                          float* __restrict__ s64) {
    __shared__ float as[64][64];
    __shared__ float ws[64][68];
    int tid = threadIdx.x;
    int n0 = blockIdx.x * 64;
    int rg = tid >> 4, cg = tid & 15;
    float acc[4][4] = {};
    for (int kc = 0; kc < 11; kc++) {
        int k0 = kc * 64;
#pragma unroll
        for (int t = 0; t < 16; t++) {
            int i = tid + t * 256; int r = i >> 6, k = i & 63;
            as[r][k] = g_final[(n0 + r) * FF + k0 + k];
        }
#pragma unroll
        for (int t = 0; t < 16; t++) {
            int i = tid + t * 256; int j = i >> 6, k = i & 63;
            ws[k][j] = w[j * FF + k0 + k];
        }
        __syncthreads();
#pragma unroll
        for (int k = 0; k < 64; k++) {
            float a0 = as[rg * 4 + 0][k], a1 = as[rg * 4 + 1][k];
            float a2 = as[rg * 4 + 2][k], a3 = as[rg * 4 + 3][k];
            float4 b4 = *(const float4*)&ws[k][cg * 4];
            acc[0][0] += a0 * b4.x; acc[0][1] += a0 * b4.y; acc[0][2] += a0 * b4.z; acc[0][3] += a0 * b4.w;
            acc[1][0] += a1 * b4.x; acc[1][1] += a1 * b4.y; acc[1][2] += a1 * b4.z; acc[1][3] += a1 * b4.w;
            acc[2][0] += a2 * b4.x; acc[2][1] += a2 * b4.y; acc[2][2] += a2 * b4.z; acc[2][3] += a2 * b4.w;
            acc[3][0] += a3 * b4.x; acc[3][1] += a3 * b4.y; acc[3][2] += a3 * b4.z; acc[3][3] += a3 * b4.w;
        }
        __syncthreads();
    }
#pragma unroll
    for (int i = 0; i < 4; i++) {
        int b = n0 + rg * 4 + i;
#pragma unroll
        for (int j = 0; j < 4; j++) {
            float v = acc[i][j] + bias[cg * 4 + j];
            s64[b * HH + cg * 4 + j] = lrelu(v);
        }
    }
}

// ---------------- scores = s64 @ t3_w^T + t3_b ----------------
__global__ void k_t3(const float* __restrict__ s64, const float* __restrict__ w,
                     const float* __restrict__ bias, float* __restrict__ scores) {
    int b = blockIdx.x * 256 + threadIdx.x;
    if (b >= BB) return;
    float a0 = bias[0], a1 = bias[1];
#pragma unroll 8
    for (int k = 0; k < 64; k++) {
        float v = s64[b * HH + k];
        a0 += v * __ldg(&w[k]);
        a1 += v * __ldg(&w[64 + k]);
    }
    scores[b * 2 + 0] = a0;
    scores[b * 2 + 1] = a1;
}

// ---------------- host ----------------
extern "C" void kernel_launch(void* const* d_in, const int* in_sizes, int n_in,
                              void* d_out, int out_size) {
    const float *h, *t1w, *t1b, *t2w, *t2b, *t3w, *t3b;
    const float *gw1[3], *gb1[3], *hw1[3], *gw2[3], *gb2[3], *hw2[3];
    const int *src[3], *dst[3], *nodes;

    if (in_sizes[1] == EE) {
        h = (const float*)d_in[0];
        src[0] = (const int*)d_in[1]; dst[0] = (const int*)d_in[2];
        src[1] = (const int*)d_in[3]; dst[1] = (const int*)d_in[4];
        src[2] = (const int*)d_in[5]; dst[2] = (const int*)d_in[6];
        nodes = (const int*)d_in[7];
        t1w = (const float*)d_in[8]; t1b = (const float*)d_in[9];
        for (int i = 0; i < 3; i++) {
            gw1[i] = (const float*)d_in[10 + 6 * i];
            gb1[i] = (const float*)d_in[11 + 6 * i];
            hw1[i] = (const float*)d_in[12 + 6 * i];
            gw2[i] = (const float*)d_in[13 + 6 * i];
            gb2[i] = (const float*)d_in[14 + 6 * i];
            hw2[i] = (const float*)d_in[15 + 6 * i];
        }
        t2w = (const float*)d_in[28]; t2b = (const float*)d_in[29];
        t3w = (const float*)d_in[30]; t3b = (const float*)d_in[31];
    } else {
        h = (const float*)d_in[0];
        t1w = (const float*)d_in[1]; t1b = (const float*)d_in[2];
        for (int i = 0; i < 3; i++) {
            gw1[i] = (const float*)d_in[3 + 3 * i];
            gb1[i] = (const float*)d_in[4 + 3 * i];
            hw1[i] = (const float*)d_in[5 + 3 * i];
            gw2[i] = (const float*)d_in[12 + 3 * i];
            gb2[i] = (const float*)d_in[13 + 3 * i];
            hw2[i] = (const float*)d_in[14 + 3 * i];
        }
        t2w = (const float*)d_in[21]; t2b = (const float*)d_in[22];
        t3w = (const float*)d_in[23]; t3b = (const float*)d_in[24];
        src[0] = (const int*)d_in[25]; dst[0] = (const int*)d_in[26];
        src[1] = (const int*)d_in[27]; dst[1] = (const int*)d_in[28];
        src[2] = (const int*)d_in[29]; dst[2] = (const int*)d_in[30];
        nodes = (const int*)d_in[31];
    }

    float* out = (float*)d_out;
    float* scores = out;
    float* s64 = out + BB * 2;

    // one-time symbol address for memset (host-side query; no allocation)
    static void* cnt_addr = nullptr;
    if (!cnt_addr) cudaGetSymbolAddress(&cnt_addr, g_cnt);

    // CSR build + t1 GEMM
    cudaMemsetAsync(cnt_addr, 0, SCAN_N * sizeof(int), 0);
    k_hist<<<dim3((E4 + 255) / 256, 3), 256>>>(dst[0], dst[1], dst[2]);
    k_scan_local<<<NBLK, 1024>>>();
    k_gemm_t1<<<(NN + 127) / 128, 256>>>(h, t1w, t1b, gw1[0], gw1[1], gw1[2]);
    k_scan_add<<<NBLK, 1024>>>();
    k_fill<<<dim3(EE / 256, 3), 256>>>(src[0], src[1], src[2], dst[0], dst[1], dst[2]);
    // layer 1
    k_agg1<<<dim3((NN + 7) / 8, 3), 256>>>(gb1[0], gb1[1], gb1[2]);
    k_gemm_h1<<<dim3((NN + 63) / 64, 3), 256>>>(hw1[0], hw1[1], hw1[2]);
    // layer 2 (selected dst only)
    k_proj2<<<(NN * 32 + 255) / 256, 256>>>(gw2[0], gw2[1], gw2[2]);
    k_agg2<<<dim3(BB / 8, 3), 256>>>(nodes, gb2[0], gb2[1], gb2[2]);
    // readout
    k_build_final<<<(BB * 512 + 255) / 256, 256>>>(nodes, h);
    k_gemm_h2<<<dim3(BB / 64, 3), 256>>>(hw2[0], hw2[1], hw2[2]);
    k_gemm_t2<<<BB / 64, 256>>>(t2w, t2b, s64);
    k_t3<<<(BB + 255) / 256, 256>>>(s64, t3w, t3b, scores);
}